// round 4
// baseline (speedup 1.0000x reference)
#include <cuda_runtime.h>

#define Bn 4
#define Nn 128
#define Cn 128
#define TFn 8
#define En 8192
#define NEGV (-1e9f)
#define EPW 8            // edges per warp
#define EPB 64           // edges per block (8 warps)

// ---------------- scratch (static device globals; no allocation) ----------------
__device__ float g_msgE[Bn*Nn*Nn*Cn];
__device__ float g_T1[Bn*Nn*Nn*TFn];          // te1 transposed: [b][dst][src][f]
__device__ float g_T2[Bn*Nn*Nn*TFn];          // te2 transposed: [b][dst][src][f]
__device__ float g_te3[Bn*Nn*Nn*TFn];         // te3 normal:     [b][src][dst][f]
__device__ float g_msg1[Bn*Nn*Cn];
__device__ float g_msg2[Bn*Nn*Cn];
__device__ float g_u1[Bn*Nn*Cn];
__device__ float g_t1[Bn*Nn*TFn];
__device__ float g_t2[Bn*Nn*TFn];
__device__ float g_t3[Bn*Nn*TFn];
__device__ float g_mgg[Bn*Cn];
__device__ float g_tg[Bn*TFn];
__device__ unsigned g_maxacc[Bn*Nn*Cn];

// ---------------- helpers ----------------
__device__ __forceinline__ unsigned fmap(float f) {
    int i = __float_as_int(f);
    return (i >= 0) ? ((unsigned)i | 0x80000000u) : ~(unsigned)i;
}
__device__ __forceinline__ float funmap(unsigned u) {
    int i = (u & 0x80000000u) ? (int)(u & 0x7FFFFFFFu) : ~(int)u;
    return __int_as_float(i);
}
__device__ __forceinline__ float wredsum(float v) {
    #pragma unroll
    for (int o = 16; o; o >>= 1) v += __shfl_xor_sync(0xffffffffu, v, o);
    return v;
}
// reduce across a 16-lane half-warp (lanes with same lane>>4)
__device__ __forceinline__ float hredsum(float v) {
    #pragma unroll
    for (int o = 8; o; o >>= 1) v += __shfl_xor_sync(0xffffffffu, v, o);
    return v;
}
__device__ __forceinline__ float brsum(float v, float* sred, int t) {
    v = wredsum(v);
    if ((t & 31) == 0) sred[t >> 5] = v;
    __syncthreads();
    v = sred[0] + sred[1] + sred[2] + sred[3];
    __syncthreads();
    return v;
}
// packed dual-fp32 FMA (sm_103a FFMA2)
__device__ __forceinline__ void fma2(unsigned long long& acc,
                                     unsigned long long a, unsigned long long b) {
    asm("fma.rn.f32x2 %0, %1, %2, %0;" : "+l"(acc) : "l"(a), "l"(b));
}
__device__ __forceinline__ unsigned long long bcast2(float x) {
    unsigned long long r;
    asm("mov.b64 %0, {%1, %1};" : "=l"(r) : "f"(x));
    return r;
}
__device__ __forceinline__ float2 unpack2(unsigned long long v) {
    float2 r;
    asm("mov.b64 {%0, %1}, %2;" : "=f"(r.x), "=f"(r.y) : "l"(v));
    return r;
}

// Thread tile: 4 rows x 8 cols. rh = lane>>4 selects row-half, cg = lane&15 selects
// 8-col group. acc[r][q] is f32x2 for cols cg*8+2q, cg*8+2q+1.
// sArows = pointer to this thread's 4 consecutive rows in shared memory.
#define GEMM48(Wp, sArows, acc)                                                   \
    _Pragma("unroll 2")                                                           \
    for (int k0 = 0; k0 < 128; k0 += 4) {                                         \
        ulonglong2 w0a = *(const ulonglong2*)&Wp[(k0+0)*128 + cg*8];              \
        ulonglong2 w0b = *(const ulonglong2*)&Wp[(k0+0)*128 + cg*8 + 4];          \
        ulonglong2 w1a = *(const ulonglong2*)&Wp[(k0+1)*128 + cg*8];              \
        ulonglong2 w1b = *(const ulonglong2*)&Wp[(k0+1)*128 + cg*8 + 4];          \
        ulonglong2 w2a = *(const ulonglong2*)&Wp[(k0+2)*128 + cg*8];              \
        ulonglong2 w2b = *(const ulonglong2*)&Wp[(k0+2)*128 + cg*8 + 4];          \
        ulonglong2 w3a = *(const ulonglong2*)&Wp[(k0+3)*128 + cg*8];              \
        ulonglong2 w3b = *(const ulonglong2*)&Wp[(k0+3)*128 + cg*8 + 4];          \
        _Pragma("unroll")                                                         \
        for (int r = 0; r < 4; r++) {                                             \
            float4 a = *(const float4*)&(sArows)[r][k0];                          \
            unsigned long long p;                                                 \
            p = bcast2(a.x);                                                      \
            fma2(acc[r][0], p, w0a.x); fma2(acc[r][1], p, w0a.y);                 \
            fma2(acc[r][2], p, w0b.x); fma2(acc[r][3], p, w0b.y);                 \
            p = bcast2(a.y);                                                      \
            fma2(acc[r][0], p, w1a.x); fma2(acc[r][1], p, w1a.y);                 \
            fma2(acc[r][2], p, w1b.x); fma2(acc[r][3], p, w1b.y);                 \
            p = bcast2(a.z);                                                      \
            fma2(acc[r][0], p, w2a.x); fma2(acc[r][1], p, w2a.y);                 \
            fma2(acc[r][2], p, w2b.x); fma2(acc[r][3], p, w2b.y);                 \
            p = bcast2(a.w);                                                      \
            fma2(acc[r][0], p, w3a.x); fma2(acc[r][1], p, w3a.y);                 \
            fma2(acc[r][2], p, w3b.x); fma2(acc[r][3], p, w3b.y);                 \
        }                                                                         \
    }

// ---------------- K1: init / zero (vectorized) ----------------
#define A4 (Bn*Nn*Nn*TFn/4)
#define B4 (En*32)
#define C4 (Bn*Nn*Cn/4)
__global__ void k_init(const int* __restrict__ eidx) {
    int idx = blockIdx.x * 256 + threadIdx.x;
    const float4 z4 = {0.f, 0.f, 0.f, 0.f};
    if (idx < 3*A4) {
        if (idx < A4)            ((float4*)g_T1)[idx] = z4;
        else if (idx < 2*A4)     ((float4*)g_T2)[idx - A4] = z4;
        else                     ((float4*)g_te3)[idx - 2*A4] = z4;
    } else if (idx < 3*A4 + B4) {
        int r = idx - 3*A4;
        int e = r >> 5, o = r & 31;
        int sg = eidx[e], dg = eidx[En + e];
        int b = sg >> 7, s = sg & 127, d = dg & 127;
        ((float4*)g_msgE)[((b*Nn + s)*Nn + d)*32 + o] = z4;
    } else if (idx < 3*A4 + B4 + C4) {
        int r = idx - 3*A4 - B4;
        unsigned m = fmap(NEGV);
        uint4 mv = {m, m, m, m};
        ((uint4*)g_maxacc)[r] = mv;
    }
}

// ---------------- K2: node & graph projections ----------------
__global__ void k_proj(const float* __restrict__ node, const float* __restrict__ graph,
                       const float* __restrict__ Wm1, const float* __restrict__ Wm2,
                       const float* __restrict__ Wu1,
                       const float* __restrict__ Wt1, const float* __restrict__ Wt2,
                       const float* __restrict__ Wt3,
                       const float* __restrict__ Wmg, const float* __restrict__ Wtg) {
    __shared__ float sx[128];
    int blk = blockIdx.x, t = threadIdx.x;
    if (blk < Bn*Nn) {
        sx[t] = node[blk*128 + t];
        __syncthreads();
        float a1 = 0.f, a2 = 0.f, a3 = 0.f;
        #pragma unroll 8
        for (int f = 0; f < 128; f++) {
            float x = sx[f];
            a1 += x * Wm1[f*128 + t];
            a2 += x * Wm2[f*128 + t];
            a3 += x * Wu1[f*128 + t];
        }
        g_msg1[blk*128 + t] = a1;
        g_msg2[blk*128 + t] = a2;
        g_u1[blk*128 + t]   = a3;
        if (t < 24) {
            int jj = t & 7;
            const float* W = (t < 8) ? Wt1 : ((t < 16) ? Wt2 : Wt3);
            float a = 0.f;
            #pragma unroll 8
            for (int f = 0; f < 128; f++) a += sx[f] * W[f*8 + jj];
            float* dstp = (t < 8) ? g_t1 : ((t < 16) ? g_t2 : g_t3);
            dstp[blk*8 + jj] = a;
        }
    } else {
        int g = blk - Bn*Nn;
        sx[t] = graph[g*128 + t];
        __syncthreads();
        float a = 0.f;
        #pragma unroll 8
        for (int f = 0; f < 128; f++) a += sx[f] * Wmg[f*128 + t];
        g_mgg[g*128 + t] = a;
        if (t < 8) {
            float bb = 0.f;
            #pragma unroll 8
            for (int f = 0; f < 128; f++) bb += sx[f] * Wtg[f*8 + t];
            g_tg[g*8 + t] = bb;
        }
    }
}

// ---------------- K3: edge projections GEMM + scatter-add ----------------
__global__ void __launch_bounds__(256, 1)
k_scatter(const float* __restrict__ eattr, const int* __restrict__ eidx,
          const float* __restrict__ Wme,
          const float* __restrict__ Wte1, const float* __restrict__ Wte2,
          const float* __restrict__ Wte3) {
    __shared__ __align__(16) float sA[EPB][128];
    int t = threadIdx.x, warp = t >> 5, lane = t & 31;
    int rh = lane >> 4, cg = lane & 15;
    int e0 = blockIdx.x * EPB + warp * EPW;
    int posMain[EPW], posT[EPW];
    #pragma unroll
    for (int i = 0; i < EPW; i++) {
        int e = e0 + i;
        *(float4*)&sA[warp*EPW + i][lane*4] = *(const float4*)&eattr[e*128 + lane*4];
        int sg = eidx[e], dg = eidx[En + e];
        int b = sg >> 7, s = sg & 127, d = dg & 127;
        posMain[i] = (b*Nn + s)*Nn + d;
        posT[i]    = (b*Nn + d)*Nn + s;
    }
    __syncwarp();
    const float (*sArows)[128] = (const float (*)[128])&sA[warp*EPW + rh*4];
    unsigned long long acc[4][4] = {};
    GEMM48(Wme, sArows, acc)
    #pragma unroll
    for (int r = 0; r < 4; r++) {
        float* dst = &g_msgE[posMain[rh*4 + r]*128 + cg*8];
        #pragma unroll
        for (int q = 0; q < 4; q++) {
            float2 v = unpack2(acc[r][q]);
            atomicAdd(dst + 2*q + 0, v.x);
            atomicAdd(dst + 2*q + 1, v.y);
        }
    }
    if (lane < 24) {
        const float* W = (lane < 8) ? Wte1 : ((lane < 16) ? Wte2 : Wte3);
        int c = lane & 7;
        float acc2[EPW] = {};
        #pragma unroll 4
        for (int k = 0; k < 128; k += 4) {
            float w0 = W[(k+0)*8 + c], w1 = W[(k+1)*8 + c];
            float w2 = W[(k+2)*8 + c], w3 = W[(k+3)*8 + c];
            #pragma unroll
            for (int i = 0; i < EPW; i++) {
                float4 a = *(const float4*)&sA[warp*EPW + i][k];
                acc2[i] += a.x*w0 + a.y*w1 + a.z*w2 + a.w*w3;
            }
        }
        #pragma unroll
        for (int i = 0; i < EPW; i++) {
            if (lane < 8)       atomicAdd(&g_T1[posT[i]*8 + c], acc2[i]);
            else if (lane < 16) atomicAdd(&g_T2[posT[i]*8 + c], acc2[i]);
            else                atomicAdd(&g_te3[posMain[i]*8 + c], acc2[i]);
        }
    }
}

// ---------------- K4: fused gather+LN1+GEMM1+LN2+GEMM2+atomicMax ----------------
__global__ void __launch_bounds__(256, 1)
k_mpnn(const int* __restrict__ eidx,
       const float* __restrict__ ln1s, const float* __restrict__ ln1o,
       const float* __restrict__ W1,
       const float* __restrict__ ln2s, const float* __restrict__ ln2o,
       const float* __restrict__ W2) {
    __shared__ __align__(16) float sY[EPB][128];
    int t = threadIdx.x, warp = t >> 5, lane = t & 31;
    int rh = lane >> 4, cg = lane & 15;
    int e0 = blockIdx.x * EPB + warp * EPW;
    int dglob[EPW];
    float4 s1 = *(const float4*)&ln1s[lane*4];
    float4 o1 = *(const float4*)&ln1o[lane*4];
    // ---- stage 1: gather + LN1 + ReLU (full warp per edge) ----
    #pragma unroll
    for (int i = 0; i < EPW; i++) {
        int e = e0 + i;
        int sg = eidx[e], dg = eidx[En + e];
        int b = sg >> 7, s = sg & 127, d = dg & 127;
        dglob[i] = b*Nn + d;
        float4 x  = *(const float4*)&g_msgE[((b*Nn + s)*Nn + d)*128 + lane*4];
        float4 m1 = *(const float4*)&g_msg1[dglob[i]*128 + lane*4];
        float4 m2 = *(const float4*)&g_msg2[(b*Nn + s)*128 + lane*4];
        float4 mg = *(const float4*)&g_mgg[b*128 + lane*4];
        x.x += m1.x + m2.x + mg.x;
        x.y += m1.y + m2.y + mg.y;
        x.z += m1.z + m2.z + mg.z;
        x.w += m1.w + m2.w + mg.w;
        float mean = wredsum(x.x + x.y + x.z + x.w) * (1.f/128.f);
        float dx = x.x - mean, dy = x.y - mean, dz = x.z - mean, dw = x.w - mean;
        float var = wredsum(dx*dx + dy*dy + dz*dz + dw*dw) * (1.f/128.f);
        float rstd = rsqrtf(var + 1e-5f);
        float4 y;
        y.x = fmaxf(s1.x * dx * rstd + o1.x, 0.f);
        y.y = fmaxf(s1.y * dy * rstd + o1.y, 0.f);
        y.z = fmaxf(s1.z * dz * rstd + o1.z, 0.f);
        y.w = fmaxf(s1.w * dw * rstd + o1.w, 0.f);
        *(float4*)&sY[warp*EPW + i][lane*4] = y;
    }
    __syncwarp();
    const float (*sArows)[128] = (const float (*)[128])&sY[warp*EPW + rh*4];
    // ---- stage 2: GEMM1 + LN2 + ReLU ----
    {
        unsigned long long acc[4][4] = {};
        GEMM48(W1, sArows, acc)
        __syncwarp();
        float4 s2a = *(const float4*)&ln2s[cg*8];
        float4 s2b = *(const float4*)&ln2s[cg*8 + 4];
        float4 o2a = *(const float4*)&ln2o[cg*8];
        float4 o2b = *(const float4*)&ln2o[cg*8 + 4];
        #pragma unroll
        for (int r = 0; r < 4; r++) {
            float2 p0 = unpack2(acc[r][0]);
            float2 p1 = unpack2(acc[r][1]);
            float2 p2 = unpack2(acc[r][2]);
            float2 p3 = unpack2(acc[r][3]);
            float mean = hredsum(p0.x+p0.y+p1.x+p1.y+p2.x+p2.y+p3.x+p3.y) * (1.f/128.f);
            float d0 = p0.x-mean, d1 = p0.y-mean, d2 = p1.x-mean, d3 = p1.y-mean;
            float d4 = p2.x-mean, d5 = p2.y-mean, d6 = p3.x-mean, d7 = p3.y-mean;
            float var = hredsum(d0*d0+d1*d1+d2*d2+d3*d3+d4*d4+d5*d5+d6*d6+d7*d7) * (1.f/128.f);
            float rstd = rsqrtf(var + 1e-5f);
            float4 ya, yb;
            ya.x = fmaxf(s2a.x * d0 * rstd + o2a.x, 0.f);
            ya.y = fmaxf(s2a.y * d1 * rstd + o2a.y, 0.f);
            ya.z = fmaxf(s2a.z * d2 * rstd + o2a.z, 0.f);
            ya.w = fmaxf(s2a.w * d3 * rstd + o2a.w, 0.f);
            yb.x = fmaxf(s2b.x * d4 * rstd + o2b.x, 0.f);
            yb.y = fmaxf(s2b.y * d5 * rstd + o2b.y, 0.f);
            yb.z = fmaxf(s2b.z * d6 * rstd + o2b.z, 0.f);
            yb.w = fmaxf(s2b.w * d7 * rstd + o2b.w, 0.f);
            *(float4*)&sY[warp*EPW + rh*4 + r][cg*8]     = ya;
            *(float4*)&sY[warp*EPW + rh*4 + r][cg*8 + 4] = yb;
        }
    }
    __syncwarp();
    // ---- stage 3: GEMM2 + atomicMax ----
    {
        unsigned long long acc[4][4] = {};
        GEMM48(W2, sArows, acc)
        #pragma unroll
        for (int r = 0; r < 4; r++) {
            unsigned* dst = &g_maxacc[dglob[rh*4 + r]*128 + cg*8];
            #pragma unroll
            for (int q = 0; q < 4; q++) {
                float2 v = unpack2(acc[r][q]);
                atomicMax(dst + 2*q + 0, fmap(v.x));
                atomicMax(dst + 2*q + 1, fmap(v.y));
            }
        }
    }
}

// ---------------- K5: per-edge triplet max + W_u3 ----------------
__global__ void k_tri(const int* __restrict__ eidx, const float* __restrict__ Wu3,
                      float* __restrict__ out2) {
    __shared__ float sw[4][8];
    __shared__ float stm[8];
    int e = blockIdx.x, t = threadIdx.x;
    int sg = eidx[e], dg = eidx[En + e];
    int b = sg >> 7, j = sg & 127, k = dg & 127;
    int i = t;
    const float4* t1v = (const float4*)g_t1;
    const float4* T1v = (const float4*)g_T1;
    const float4* T2v = (const float4*)g_T2;
    int ia = (b*Nn + i) * 2;
    int i1 = ((b*Nn + j)*Nn + i) * 2;
    int i2 = ((b*Nn + k)*Nn + i) * 2;
    float4 a0 = t1v[ia],   a1 = t1v[ia+1];
    float4 b0 = T1v[i1],   b1 = T1v[i1+1];
    float4 c0 = T2v[i2],   c1 = T2v[i2+1];
    float v[8];
    v[0] = a0.x + b0.x + c0.x;  v[1] = a0.y + b0.y + c0.y;
    v[2] = a0.z + b0.z + c0.z;  v[3] = a0.w + b0.w + c0.w;
    v[4] = a1.x + b1.x + c1.x;  v[5] = a1.y + b1.y + c1.y;
    v[6] = a1.z + b1.z + c1.z;  v[7] = a1.w + b1.w + c1.w;
    #pragma unroll
    for (int off = 16; off; off >>= 1) {
        #pragma unroll
        for (int f = 0; f < 8; f++)
            v[f] = fmaxf(v[f], __shfl_xor_sync(0xffffffffu, v[f], off));
    }
    if ((t & 31) == 0) {
        int w = t >> 5;
        #pragma unroll
        for (int f = 0; f < 8; f++) sw[w][f] = v[f];
    }
    __syncthreads();
    if (t < 8) {
        float m = fmaxf(fmaxf(sw[0][t], sw[1][t]), fmaxf(sw[2][t], sw[3][t]));
        m += g_t2[(b*Nn + j)*8 + t] + g_t3[(b*Nn + k)*8 + t]
           + g_te3[((b*Nn + j)*Nn + k)*8 + t] + g_tg[b*8 + t];
        stm[t] = m;
    }
    __syncthreads();
    float acc = 0.f;
    #pragma unroll
    for (int f = 0; f < 8; f++) acc += stm[f] * Wu3[f*128 + t];
    out2[e*128 + t] = fmaxf(acc, 0.f);
}

// ---------------- K6: final ret = LN(u1 + max @ W_u2) ----------------
__global__ void k_final(const float* __restrict__ Wu2,
                        const float* __restrict__ lnfs, const float* __restrict__ lnfo,
                        float* __restrict__ out1) {
    __shared__ float sm[128];
    __shared__ float sred[4];
    int n = blockIdx.x, t = threadIdx.x;
    sm[t] = funmap(g_maxacc[n*128 + t]);
    __syncthreads();
    float acc = g_u1[n*128 + t];
    #pragma unroll 8
    for (int f = 0; f < 128; f++) acc += sm[f] * Wu2[f*128 + t];
    float mean = brsum(acc, sred, t) * (1.f/128.f);
    float dmu = acc - mean;
    float var = brsum(dmu*dmu, sred, t) * (1.f/128.f);
    out1[n*128 + t] = lnfs[t] * dmu * rsqrtf(var + 1e-5f) + lnfo[t];
}

// ---------------- launch ----------------
extern "C" void kernel_launch(void* const* d_in, const int* in_sizes, int n_in,
                              void* d_out, int out_size) {
    const float* node_fts  = (const float*)d_in[0];
    const float* edge_attr = (const float*)d_in[1];
    const float* graph_fts = (const float*)d_in[2];
    const float* W_tri1 = (const float*)d_in[3];
    const float* W_tri2 = (const float*)d_in[4];
    const float* W_tri3 = (const float*)d_in[5];
    const float* W_te1  = (const float*)d_in[6];
    const float* W_te2  = (const float*)d_in[7];
    const float* W_te3  = (const float*)d_in[8];
    const float* W_tg   = (const float*)d_in[9];
    const float* W_m1   = (const float*)d_in[10];
    const float* W_m2   = (const float*)d_in[11];
    const float* W_me   = (const float*)d_in[12];
    const float* W_mg   = (const float*)d_in[13];
    const float* ln1_s  = (const float*)d_in[14];
    const float* ln1_o  = (const float*)d_in[15];
    const float* W_mlp1 = (const float*)d_in[16];
    const float* ln2_s  = (const float*)d_in[17];
    const float* ln2_o  = (const float*)d_in[18];
    const float* W_mlp2 = (const float*)d_in[19];
    const float* W_u1   = (const float*)d_in[20];
    const float* W_u2   = (const float*)d_in[21];
    const float* W_u3   = (const float*)d_in[22];
    const float* lnf_s  = (const float*)d_in[23];
    const float* lnf_o  = (const float*)d_in[24];
    const int*   eidx   = (const int*)d_in[25];

    float* out1 = (float*)d_out;                 // ret      [512,128]
    float* out2 = out1 + Bn*Nn*Cn;               // tri gath [8192,128]

    int init_total = 3*A4 + B4 + C4;
    k_init<<<(init_total + 255)/256, 256>>>(eidx);
    k_proj<<<Bn*Nn + Bn, 128>>>(node_fts, graph_fts, W_m1, W_m2, W_u1,
                                W_tri1, W_tri2, W_tri3, W_mg, W_tg);
    k_scatter<<<En/EPB, 256>>>(edge_attr, eidx, W_me, W_te1, W_te2, W_te3);
    k_mpnn<<<En/EPB, 256>>>(eidx, ln1_s, ln1_o, W_mlp1, ln2_s, ln2_o, W_mlp2);
    k_tri<<<En, 128>>>(eidx, W_u3, out2);
    k_final<<<Bn*Nn, 128>>>(W_u2, lnf_s, lnf_o, out1);
}

// round 5
// speedup vs baseline: 1.1291x; 1.1291x over previous
#include <cuda_runtime.h>

#define Bn 4
#define Nn 128
#define Cn 128
#define TFn 8
#define En 8192
#define NEGV (-1e9f)
#define EPW 4            // edges per warp
#define EPB 32           // edges per block (8 warps)

// ---------------- scratch (static device globals; no allocation) ----------------
__device__ float g_msgE[Bn*Nn*Nn*Cn];
__device__ float g_T1[Bn*Nn*Nn*TFn];          // te1 transposed: [b][dst][src][f]
__device__ float g_T2[Bn*Nn*Nn*TFn];          // te2 transposed: [b][dst][src][f]
__device__ float g_te3[Bn*Nn*Nn*TFn];         // te3 normal:     [b][src][dst][f]
__device__ float g_msg1[Bn*Nn*Cn];
__device__ float g_msg2[Bn*Nn*Cn];
__device__ float g_u1[Bn*Nn*Cn];
__device__ float g_t1[Bn*Nn*TFn];
__device__ float g_t2[Bn*Nn*TFn];
__device__ float g_t3[Bn*Nn*TFn];
__device__ float g_mgg[Bn*Cn];
__device__ float g_tg[Bn*TFn];
__device__ unsigned g_maxacc[Bn*Nn*Cn];

// ---------------- helpers ----------------
__device__ __forceinline__ unsigned fmap(float f) {
    int i = __float_as_int(f);
    return (i >= 0) ? ((unsigned)i | 0x80000000u) : ~(unsigned)i;
}
__device__ __forceinline__ float funmap(unsigned u) {
    int i = (u & 0x80000000u) ? (int)(u & 0x7FFFFFFFu) : ~(int)u;
    return __int_as_float(i);
}
__device__ __forceinline__ float wredsum(float v) {
    #pragma unroll
    for (int o = 16; o; o >>= 1) v += __shfl_xor_sync(0xffffffffu, v, o);
    return v;
}
__device__ __forceinline__ float brsum(float v, float* sred, int t) {
    v = wredsum(v);
    if ((t & 31) == 0) sred[t >> 5] = v;
    __syncthreads();
    v = sred[0] + sred[1] + sred[2] + sred[3];
    __syncthreads();
    return v;
}
// packed dual-fp32 FMA (sm_103a FFMA2)
__device__ __forceinline__ void fma2(unsigned long long& acc,
                                     unsigned long long a, unsigned long long b) {
    asm("fma.rn.f32x2 %0, %1, %2, %0;" : "+l"(acc) : "l"(a), "l"(b));
}
__device__ __forceinline__ unsigned long long bcast2(float x) {
    unsigned long long r;
    asm("mov.b64 %0, {%1, %1};" : "=l"(r) : "f"(x));
    return r;
}
__device__ __forceinline__ float2 unpack2(unsigned long long v) {
    float2 r;
    asm("mov.b64 {%0, %1}, %2;" : "=f"(r.x), "=f"(r.y) : "l"(v));
    return r;
}

// GEMM tile: warp owns 4 rows; each lane owns cols lane*4..lane*4+3 (2 f32x2 accs/row).
// Per chunk: 4 LDG.128 (W), 4 LDS.128 (A), 32 FFMA2.
#define GEMM44(Wp, sArows, acc)                                                   \
    _Pragma("unroll 4")                                                           \
    for (int k0 = 0; k0 < 128; k0 += 4) {                                         \
        ulonglong2 w0 = *(const ulonglong2*)&Wp[(k0+0)*128 + lane*4];             \
        ulonglong2 w1 = *(const ulonglong2*)&Wp[(k0+1)*128 + lane*4];             \
        ulonglong2 w2 = *(const ulonglong2*)&Wp[(k0+2)*128 + lane*4];             \
        ulonglong2 w3 = *(const ulonglong2*)&Wp[(k0+3)*128 + lane*4];             \
        _Pragma("unroll")                                                         \
        for (int r = 0; r < EPW; r++) {                                           \
            float4 a = *(const float4*)&(sArows)[r][k0];                          \
            unsigned long long p;                                                 \
            p = bcast2(a.x); fma2(acc[r][0], p, w0.x); fma2(acc[r][1], p, w0.y);  \
            p = bcast2(a.y); fma2(acc[r][0], p, w1.x); fma2(acc[r][1], p, w1.y);  \
            p = bcast2(a.z); fma2(acc[r][0], p, w2.x); fma2(acc[r][1], p, w2.y);  \
            p = bcast2(a.w); fma2(acc[r][0], p, w3.x); fma2(acc[r][1], p, w3.y);  \
        }                                                                         \
    }

// ---------------- K1: init / zero (vectorized) ----------------
#define A4 (Bn*Nn*Nn*TFn/4)
#define B4 (En*32)
#define C4 (Bn*Nn*Cn/4)
__global__ void k_init(const int* __restrict__ eidx) {
    int idx = blockIdx.x * 256 + threadIdx.x;
    const float4 z4 = {0.f, 0.f, 0.f, 0.f};
    if (idx < 3*A4) {
        if (idx < A4)            ((float4*)g_T1)[idx] = z4;
        else if (idx < 2*A4)     ((float4*)g_T2)[idx - A4] = z4;
        else                     ((float4*)g_te3)[idx - 2*A4] = z4;
    } else if (idx < 3*A4 + B4) {
        int r = idx - 3*A4;
        int e = r >> 5, o = r & 31;
        int sg = eidx[e], dg = eidx[En + e];
        int b = sg >> 7, s = sg & 127, d = dg & 127;
        ((float4*)g_msgE)[((b*Nn + s)*Nn + d)*32 + o] = z4;
    } else if (idx < 3*A4 + B4 + C4) {
        int r = idx - 3*A4 - B4;
        unsigned m = fmap(NEGV);
        uint4 mv = {m, m, m, m};
        ((uint4*)g_maxacc)[r] = mv;
    }
}

// ---------------- K2: node & graph projections ----------------
__global__ void k_proj(const float* __restrict__ node, const float* __restrict__ graph,
                       const float* __restrict__ Wm1, const float* __restrict__ Wm2,
                       const float* __restrict__ Wu1,
                       const float* __restrict__ Wt1, const float* __restrict__ Wt2,
                       const float* __restrict__ Wt3,
                       const float* __restrict__ Wmg, const float* __restrict__ Wtg) {
    __shared__ float sx[128];
    int blk = blockIdx.x, t = threadIdx.x;
    if (blk < Bn*Nn) {
        sx[t] = node[blk*128 + t];
        __syncthreads();
        float a1 = 0.f, a2 = 0.f, a3 = 0.f;
        #pragma unroll 8
        for (int f = 0; f < 128; f++) {
            float x = sx[f];
            a1 += x * Wm1[f*128 + t];
            a2 += x * Wm2[f*128 + t];
            a3 += x * Wu1[f*128 + t];
        }
        g_msg1[blk*128 + t] = a1;
        g_msg2[blk*128 + t] = a2;
        g_u1[blk*128 + t]   = a3;
        if (t < 24) {
            int jj = t & 7;
            const float* W = (t < 8) ? Wt1 : ((t < 16) ? Wt2 : Wt3);
            float a = 0.f;
            #pragma unroll 8
            for (int f = 0; f < 128; f++) a += sx[f] * W[f*8 + jj];
            float* dstp = (t < 8) ? g_t1 : ((t < 16) ? g_t2 : g_t3);
            dstp[blk*8 + jj] = a;
        }
    } else {
        int g = blk - Bn*Nn;
        sx[t] = graph[g*128 + t];
        __syncthreads();
        float a = 0.f;
        #pragma unroll 8
        for (int f = 0; f < 128; f++) a += sx[f] * Wmg[f*128 + t];
        g_mgg[g*128 + t] = a;
        if (t < 8) {
            float bb = 0.f;
            #pragma unroll 8
            for (int f = 0; f < 128; f++) bb += sx[f] * Wtg[f*8 + t];
            g_tg[g*8 + t] = bb;
        }
    }
}

// ---------------- K3: edge projections GEMM + scatter-add ----------------
__global__ void k_scatter(const float* __restrict__ eattr, const int* __restrict__ eidx,
                          const float* __restrict__ Wme,
                          const float* __restrict__ Wte1, const float* __restrict__ Wte2,
                          const float* __restrict__ Wte3) {
    __shared__ __align__(16) float sA[EPB][128];
    int t = threadIdx.x, warp = t >> 5, lane = t & 31;
    int e0 = blockIdx.x * EPB + warp * EPW;
    int posMain[EPW], posT[EPW];
    #pragma unroll
    for (int i = 0; i < EPW; i++) {
        int e = e0 + i;
        *(float4*)&sA[warp*EPW + i][lane*4] = *(const float4*)&eattr[e*128 + lane*4];
        int sg = eidx[e], dg = eidx[En + e];
        int b = sg >> 7, s = sg & 127, d = dg & 127;
        posMain[i] = (b*Nn + s)*Nn + d;
        posT[i]    = (b*Nn + d)*Nn + s;
    }
    __syncwarp();
    const float (*sArows)[128] = (const float (*)[128])&sA[warp*EPW];
    unsigned long long acc[EPW][2] = {};
    GEMM44(Wme, sArows, acc)
    #pragma unroll
    for (int i = 0; i < EPW; i++) {
        float2 v01 = unpack2(acc[i][0]);
        float2 v23 = unpack2(acc[i][1]);
        float* dst = &g_msgE[posMain[i]*128 + lane*4];
        atomicAdd(dst + 0, v01.x);
        atomicAdd(dst + 1, v01.y);
        atomicAdd(dst + 2, v23.x);
        atomicAdd(dst + 3, v23.y);
    }
    if (lane < 24) {
        const float* W = (lane < 8) ? Wte1 : ((lane < 16) ? Wte2 : Wte3);
        int c = lane & 7;
        float acc2[EPW] = {};
        #pragma unroll 4
        for (int k = 0; k < 128; k += 4) {
            float w0 = W[(k+0)*8 + c], w1 = W[(k+1)*8 + c];
            float w2 = W[(k+2)*8 + c], w3 = W[(k+3)*8 + c];
            #pragma unroll
            for (int i = 0; i < EPW; i++) {
                float4 a = *(const float4*)&sA[warp*EPW + i][k];
                acc2[i] += a.x*w0 + a.y*w1 + a.z*w2 + a.w*w3;
            }
        }
        #pragma unroll
        for (int i = 0; i < EPW; i++) {
            if (lane < 8)       atomicAdd(&g_T1[posT[i]*8 + c], acc2[i]);
            else if (lane < 16) atomicAdd(&g_T2[posT[i]*8 + c], acc2[i]);
            else                atomicAdd(&g_te3[posMain[i]*8 + c], acc2[i]);
        }
    }
}

// ---------------- K4: fused gather+LN1+GEMM1+LN2+GEMM2+atomicMax ----------------
__global__ void k_mpnn(const int* __restrict__ eidx,
                       const float* __restrict__ ln1s, const float* __restrict__ ln1o,
                       const float* __restrict__ W1,
                       const float* __restrict__ ln2s, const float* __restrict__ ln2o,
                       const float* __restrict__ W2) {
    __shared__ __align__(16) float sY[EPB][128];
    int t = threadIdx.x, warp = t >> 5, lane = t & 31;
    int e0 = blockIdx.x * EPB + warp * EPW;
    int dglob[EPW];
    float4 s1 = *(const float4*)&ln1s[lane*4];
    float4 o1 = *(const float4*)&ln1o[lane*4];
    // ---- stage 1: gather + LN1 + ReLU ----
    #pragma unroll
    for (int i = 0; i < EPW; i++) {
        int e = e0 + i;
        int sg = eidx[e], dg = eidx[En + e];
        int b = sg >> 7, s = sg & 127, d = dg & 127;
        dglob[i] = b*Nn + d;
        float4 x  = *(const float4*)&g_msgE[((b*Nn + s)*Nn + d)*128 + lane*4];
        float4 m1 = *(const float4*)&g_msg1[dglob[i]*128 + lane*4];
        float4 m2 = *(const float4*)&g_msg2[(b*Nn + s)*128 + lane*4];
        float4 mg = *(const float4*)&g_mgg[b*128 + lane*4];
        x.x += m1.x + m2.x + mg.x;
        x.y += m1.y + m2.y + mg.y;
        x.z += m1.z + m2.z + mg.z;
        x.w += m1.w + m2.w + mg.w;
        float mean = wredsum(x.x + x.y + x.z + x.w) * (1.f/128.f);
        float dx = x.x - mean, dy = x.y - mean, dz = x.z - mean, dw = x.w - mean;
        float var = wredsum(dx*dx + dy*dy + dz*dz + dw*dw) * (1.f/128.f);
        float rstd = rsqrtf(var + 1e-5f);
        float4 y;
        y.x = fmaxf(s1.x * dx * rstd + o1.x, 0.f);
        y.y = fmaxf(s1.y * dy * rstd + o1.y, 0.f);
        y.z = fmaxf(s1.z * dz * rstd + o1.z, 0.f);
        y.w = fmaxf(s1.w * dw * rstd + o1.w, 0.f);
        *(float4*)&sY[warp*EPW + i][lane*4] = y;
    }
    __syncwarp();
    const float (*sArows)[128] = (const float (*)[128])&sY[warp*EPW];
    // ---- stage 2: GEMM1 + LN2 + ReLU ----
    float4 s2 = *(const float4*)&ln2s[lane*4];
    float4 o2 = *(const float4*)&ln2o[lane*4];
    {
        unsigned long long acc[EPW][2] = {};
        GEMM44(W1, sArows, acc)
        __syncwarp();
        #pragma unroll
        for (int i = 0; i < EPW; i++) {
            float2 v01 = unpack2(acc[i][0]);
            float2 v23 = unpack2(acc[i][1]);
            float mean = wredsum(v01.x + v01.y + v23.x + v23.y) * (1.f/128.f);
            float d0 = v01.x - mean, d1 = v01.y - mean;
            float d2 = v23.x - mean, d3 = v23.y - mean;
            float var = wredsum(d0*d0 + d1*d1 + d2*d2 + d3*d3) * (1.f/128.f);
            float rstd = rsqrtf(var + 1e-5f);
            float4 y;
            y.x = fmaxf(s2.x * d0 * rstd + o2.x, 0.f);
            y.y = fmaxf(s2.y * d1 * rstd + o2.y, 0.f);
            y.z = fmaxf(s2.z * d2 * rstd + o2.z, 0.f);
            y.w = fmaxf(s2.w * d3 * rstd + o2.w, 0.f);
            *(float4*)&sY[warp*EPW + i][lane*4] = y;
        }
    }
    __syncwarp();
    // ---- stage 3: GEMM2 + atomicMax ----
    {
        unsigned long long acc[EPW][2] = {};
        GEMM44(W2, sArows, acc)
        #pragma unroll
        for (int i = 0; i < EPW; i++) {
            float2 v01 = unpack2(acc[i][0]);
            float2 v23 = unpack2(acc[i][1]);
            unsigned* dst = &g_maxacc[dglob[i]*128 + lane*4];
            atomicMax(dst + 0, fmap(v01.x));
            atomicMax(dst + 1, fmap(v01.y));
            atomicMax(dst + 2, fmap(v23.x));
            atomicMax(dst + 3, fmap(v23.y));
        }
    }
}

// ---------------- K5: per-edge triplet max + W_u3 ----------------
__global__ void k_tri(const int* __restrict__ eidx, const float* __restrict__ Wu3,
                      float* __restrict__ out2) {
    __shared__ float sw[4][8];
    __shared__ float stm[8];
    int e = blockIdx.x, t = threadIdx.x;
    int sg = eidx[e], dg = eidx[En + e];
    int b = sg >> 7, j = sg & 127, k = dg & 127;
    int i = t;
    const float4* t1v = (const float4*)g_t1;
    const float4* T1v = (const float4*)g_T1;
    const float4* T2v = (const float4*)g_T2;
    int ia = (b*Nn + i) * 2;
    int i1 = ((b*Nn + j)*Nn + i) * 2;
    int i2 = ((b*Nn + k)*Nn + i) * 2;
    float4 a0 = t1v[ia],   a1 = t1v[ia+1];
    float4 b0 = T1v[i1],   b1 = T1v[i1+1];
    float4 c0 = T2v[i2],   c1 = T2v[i2+1];
    float v[8];
    v[0] = a0.x + b0.x + c0.x;  v[1] = a0.y + b0.y + c0.y;
    v[2] = a0.z + b0.z + c0.z;  v[3] = a0.w + b0.w + c0.w;
    v[4] = a1.x + b1.x + c1.x;  v[5] = a1.y + b1.y + c1.y;
    v[6] = a1.z + b1.z + c1.z;  v[7] = a1.w + b1.w + c1.w;
    #pragma unroll
    for (int off = 16; off; off >>= 1) {
        #pragma unroll
        for (int f = 0; f < 8; f++)
            v[f] = fmaxf(v[f], __shfl_xor_sync(0xffffffffu, v[f], off));
    }
    if ((t & 31) == 0) {
        int w = t >> 5;
        #pragma unroll
        for (int f = 0; f < 8; f++) sw[w][f] = v[f];
    }
    __syncthreads();
    if (t < 8) {
        float m = fmaxf(fmaxf(sw[0][t], sw[1][t]), fmaxf(sw[2][t], sw[3][t]));
        m += g_t2[(b*Nn + j)*8 + t] + g_t3[(b*Nn + k)*8 + t]
           + g_te3[((b*Nn + j)*Nn + k)*8 + t] + g_tg[b*8 + t];
        stm[t] = m;
    }
    __syncthreads();
    float acc = 0.f;
    #pragma unroll
    for (int f = 0; f < 8; f++) acc += stm[f] * Wu3[f*128 + t];
    out2[e*128 + t] = fmaxf(acc, 0.f);
}

// ---------------- K6: final ret = LN(u1 + max @ W_u2) ----------------
__global__ void k_final(const float* __restrict__ Wu2,
                        const float* __restrict__ lnfs, const float* __restrict__ lnfo,
                        float* __restrict__ out1) {
    __shared__ float sm[128];
    __shared__ float sred[4];
    int n = blockIdx.x, t = threadIdx.x;
    sm[t] = funmap(g_maxacc[n*128 + t]);
    __syncthreads();
    float acc = g_u1[n*128 + t];
    #pragma unroll 8
    for (int f = 0; f < 128; f++) acc += sm[f] * Wu2[f*128 + t];
    float mean = brsum(acc, sred, t) * (1.f/128.f);
    float dmu = acc - mean;
    float var = brsum(dmu*dmu, sred, t) * (1.f/128.f);
    out1[n*128 + t] = lnfs[t] * dmu * rsqrtf(var + 1e-5f) + lnfo[t];
}

// ---------------- launch (multi-stream fork/join inside capture) ----------------
extern "C" void kernel_launch(void* const* d_in, const int* in_sizes, int n_in,
                              void* d_out, int out_size) {
    const float* node_fts  = (const float*)d_in[0];
    const float* edge_attr = (const float*)d_in[1];
    const float* graph_fts = (const float*)d_in[2];
    const float* W_tri1 = (const float*)d_in[3];
    const float* W_tri2 = (const float*)d_in[4];
    const float* W_tri3 = (const float*)d_in[5];
    const float* W_te1  = (const float*)d_in[6];
    const float* W_te2  = (const float*)d_in[7];
    const float* W_te3  = (const float*)d_in[8];
    const float* W_tg   = (const float*)d_in[9];
    const float* W_m1   = (const float*)d_in[10];
    const float* W_m2   = (const float*)d_in[11];
    const float* W_me   = (const float*)d_in[12];
    const float* W_mg   = (const float*)d_in[13];
    const float* ln1_s  = (const float*)d_in[14];
    const float* ln1_o  = (const float*)d_in[15];
    const float* W_mlp1 = (const float*)d_in[16];
    const float* ln2_s  = (const float*)d_in[17];
    const float* ln2_o  = (const float*)d_in[18];
    const float* W_mlp2 = (const float*)d_in[19];
    const float* W_u1   = (const float*)d_in[20];
    const float* W_u2   = (const float*)d_in[21];
    const float* W_u3   = (const float*)d_in[22];
    const float* lnf_s  = (const float*)d_in[23];
    const float* lnf_o  = (const float*)d_in[24];
    const int*   eidx   = (const int*)d_in[25];

    float* out1 = (float*)d_out;                 // ret      [512,128]
    float* out2 = out1 + Bn*Nn*Cn;               // tri gath [8192,128]

    // streams/events created once on the first (non-captured correctness) call
    static cudaStream_t s2 = 0, s3 = 0;
    static cudaEvent_t eFork = 0, eProj = 0, eScat = 0, eTri = 0;
    if (!s2) {
        cudaStreamCreateWithFlags(&s2, cudaStreamNonBlocking);
        cudaStreamCreateWithFlags(&s3, cudaStreamNonBlocking);
        cudaEventCreateWithFlags(&eFork, cudaEventDisableTiming);
        cudaEventCreateWithFlags(&eProj, cudaEventDisableTiming);
        cudaEventCreateWithFlags(&eScat, cudaEventDisableTiming);
        cudaEventCreateWithFlags(&eTri,  cudaEventDisableTiming);
    }

    // fork
    cudaEventRecord(eFork, 0);
    cudaStreamWaitEvent(s2, eFork, 0);
    cudaStreamWaitEvent(s3, eFork, 0);

    // s2: projections (independent of init/scatter)
    k_proj<<<Bn*Nn + Bn, 128, 0, s2>>>(node_fts, graph_fts, W_m1, W_m2, W_u1,
                                       W_tri1, W_tri2, W_tri3, W_mg, W_tg);
    cudaEventRecord(eProj, s2);

    // main: init -> scatter
    int init_total = 3*A4 + B4 + C4;
    k_init<<<(init_total + 255)/256, 256>>>(eidx);
    k_scatter<<<En/EPB, 256>>>(edge_attr, eidx, W_me, W_te1, W_te2, W_te3);
    cudaEventRecord(eScat, 0);

    // s3: triplet path (needs scatter + proj), runs concurrently with k_mpnn
    cudaStreamWaitEvent(s3, eScat, 0);
    cudaStreamWaitEvent(s3, eProj, 0);
    k_tri<<<En, 128, 0, s3>>>(eidx, W_u3, out2);
    cudaEventRecord(eTri, s3);

    // main: mpnn (needs scatter + proj) -> final
    cudaStreamWaitEvent(0, eProj, 0);
    k_mpnn<<<En/EPB, 256>>>(eidx, ln1_s, ln1_o, W_mlp1, ln2_s, ln2_o, W_mlp2);
    k_final<<<Bn*Nn, 128>>>(W_u2, lnf_s, lnf_o, out1);

    // join
    cudaStreamWaitEvent(0, eTri, 0);
}

// round 6
// speedup vs baseline: 1.1885x; 1.0526x over previous
#include <cuda_runtime.h>

#define Bn 4
#define Nn 128
#define Cn 128
#define TFn 8
#define En 8192
#define NEGV (-1e9f)
#define EPW 4            // edges per warp (GEMM kernels)
#define EPB 32           // edges per block (8 warps)

// ---------------- scratch (static device globals; no allocation) ----------------
__device__ float g_msgE[Bn*Nn*Nn*Cn];
__device__ float g_T1[Bn*Nn*Nn*TFn];          // te1 transposed: [b][dst][src][f]
__device__ float g_T2[Bn*Nn*Nn*TFn];          // te2 transposed: [b][dst][src][f]
__device__ float g_te3[Bn*Nn*Nn*TFn];         // te3 normal:     [b][src][dst][f]
__device__ float g_msg1[Bn*Nn*Cn];
__device__ float g_msg2[Bn*Nn*Cn];
__device__ float g_u1[Bn*Nn*Cn];
__device__ float g_t1[Bn*Nn*TFn];
__device__ float g_t2[Bn*Nn*TFn];
__device__ float g_t3[Bn*Nn*TFn];
__device__ float g_mgg[Bn*Cn];
__device__ float g_tg[Bn*TFn];
__device__ unsigned g_maxacc[Bn*Nn*Cn];
// edge grouping by source key g = b*128+j  (g == edge_index[0][e])
__device__ int g_cnt[Bn*Nn];
__device__ int g_offs[Bn*Nn];
__device__ int g_elist[En];

// ---------------- helpers ----------------
__device__ __forceinline__ unsigned fmap(float f) {
    int i = __float_as_int(f);
    return (i >= 0) ? ((unsigned)i | 0x80000000u) : ~(unsigned)i;
}
__device__ __forceinline__ float funmap(unsigned u) {
    int i = (u & 0x80000000u) ? (int)(u & 0x7FFFFFFFu) : ~(int)u;
    return __int_as_float(i);
}
__device__ __forceinline__ float wredsum(float v) {
    #pragma unroll
    for (int o = 16; o; o >>= 1) v += __shfl_xor_sync(0xffffffffu, v, o);
    return v;
}
__device__ __forceinline__ float brsum(float v, float* sred, int t) {
    v = wredsum(v);
    if ((t & 31) == 0) sred[t >> 5] = v;
    __syncthreads();
    v = sred[0] + sred[1] + sred[2] + sred[3];
    __syncthreads();
    return v;
}
// packed dual-fp32 FMA (sm_103a FFMA2)
__device__ __forceinline__ void fma2(unsigned long long& acc,
                                     unsigned long long a, unsigned long long b) {
    asm("fma.rn.f32x2 %0, %1, %2, %0;" : "+l"(acc) : "l"(a), "l"(b));
}
__device__ __forceinline__ unsigned long long bcast2(float x) {
    unsigned long long r;
    asm("mov.b64 %0, {%1, %1};" : "=l"(r) : "f"(x));
    return r;
}
__device__ __forceinline__ float2 unpack2(unsigned long long v) {
    float2 r;
    asm("mov.b64 {%0, %1}, %2;" : "=f"(r.x), "=f"(r.y) : "l"(v));
    return r;
}

// GEMM tile: warp owns 4 rows; each lane owns cols lane*4..lane*4+3 (2 f32x2 accs/row).
#define GEMM44(Wp, sArows, acc)                                                   \
    _Pragma("unroll 4")                                                           \
    for (int k0 = 0; k0 < 128; k0 += 4) {                                         \
        ulonglong2 w0 = *(const ulonglong2*)&Wp[(k0+0)*128 + lane*4];             \
        ulonglong2 w1 = *(const ulonglong2*)&Wp[(k0+1)*128 + lane*4];             \
        ulonglong2 w2 = *(const ulonglong2*)&Wp[(k0+2)*128 + lane*4];             \
        ulonglong2 w3 = *(const ulonglong2*)&Wp[(k0+3)*128 + lane*4];             \
        _Pragma("unroll")                                                         \
        for (int r = 0; r < EPW; r++) {                                           \
            float4 a = *(const float4*)&(sArows)[r][k0];                          \
            unsigned long long p;                                                 \
            p = bcast2(a.x); fma2(acc[r][0], p, w0.x); fma2(acc[r][1], p, w0.y);  \
            p = bcast2(a.y); fma2(acc[r][0], p, w1.x); fma2(acc[r][1], p, w1.y);  \
            p = bcast2(a.z); fma2(acc[r][0], p, w2.x); fma2(acc[r][1], p, w2.y);  \
            p = bcast2(a.w); fma2(acc[r][0], p, w3.x); fma2(acc[r][1], p, w3.y);  \
        }                                                                         \
    }

// ---------------- K1: init / zero (vectorized) ----------------
#define A4 (Bn*Nn*Nn*TFn/4)
#define B4 (En*32)
#define C4 (Bn*Nn*Cn/4)
__global__ void k_init(const int* __restrict__ eidx) {
    int idx = blockIdx.x * 256 + threadIdx.x;
    const float4 z4 = {0.f, 0.f, 0.f, 0.f};
    if (idx < 3*A4) {
        if (idx < A4)            ((float4*)g_T1)[idx] = z4;
        else if (idx < 2*A4)     ((float4*)g_T2)[idx - A4] = z4;
        else                     ((float4*)g_te3)[idx - 2*A4] = z4;
    } else if (idx < 3*A4 + B4) {
        int r = idx - 3*A4;
        int e = r >> 5, o = r & 31;
        int sg = eidx[e], dg = eidx[En + e];
        int b = sg >> 7, s = sg & 127, d = dg & 127;
        ((float4*)g_msgE)[((b*Nn + s)*Nn + d)*32 + o] = z4;
    } else if (idx < 3*A4 + B4 + C4) {
        int r = idx - 3*A4 - B4;
        unsigned m = fmap(NEGV);
        uint4 mv = {m, m, m, m};
        ((uint4*)g_maxacc)[r] = mv;
    }
}

// ---------------- K2: node & graph projections ----------------
__global__ void k_proj(const float* __restrict__ node, const float* __restrict__ graph,
                       const float* __restrict__ Wm1, const float* __restrict__ Wm2,
                       const float* __restrict__ Wu1,
                       const float* __restrict__ Wt1, const float* __restrict__ Wt2,
                       const float* __restrict__ Wt3,
                       const float* __restrict__ Wmg, const float* __restrict__ Wtg) {
    __shared__ float sx[128];
    int blk = blockIdx.x, t = threadIdx.x;
    if (blk < Bn*Nn) {
        sx[t] = node[blk*128 + t];
        __syncthreads();
        float a1 = 0.f, a2 = 0.f, a3 = 0.f;
        #pragma unroll 8
        for (int f = 0; f < 128; f++) {
            float x = sx[f];
            a1 += x * Wm1[f*128 + t];
            a2 += x * Wm2[f*128 + t];
            a3 += x * Wu1[f*128 + t];
        }
        g_msg1[blk*128 + t] = a1;
        g_msg2[blk*128 + t] = a2;
        g_u1[blk*128 + t]   = a3;
        if (t < 24) {
            int jj = t & 7;
            const float* W = (t < 8) ? Wt1 : ((t < 16) ? Wt2 : Wt3);
            float a = 0.f;
            #pragma unroll 8
            for (int f = 0; f < 128; f++) a += sx[f] * W[f*8 + jj];
            float* dstp = (t < 8) ? g_t1 : ((t < 16) ? g_t2 : g_t3);
            dstp[blk*8 + jj] = a;
        }
    } else {
        int g = blk - Bn*Nn;
        sx[t] = graph[g*128 + t];
        __syncthreads();
        float a = 0.f;
        #pragma unroll 8
        for (int f = 0; f < 128; f++) a += sx[f] * Wmg[f*128 + t];
        g_mgg[g*128 + t] = a;
        if (t < 8) {
            float bb = 0.f;
            #pragma unroll 8
            for (int f = 0; f < 128; f++) bb += sx[f] * Wtg[f*8 + t];
            g_tg[g*8 + t] = bb;
        }
    }
}

// ---------------- K2b: build edge groups (single block, 512 threads) ----------------
__global__ void k_group(const int* __restrict__ eidx) {
    __shared__ int scnt[512], soff[512], scur[512];
    int t = threadIdx.x;
    scnt[t] = 0;
    __syncthreads();
    #pragma unroll
    for (int r = 0; r < En/512; r++)
        atomicAdd(&scnt[eidx[r*512 + t]], 1);
    __syncthreads();
    soff[t] = scnt[t];
    __syncthreads();
    for (int d = 1; d < 512; d <<= 1) {
        int v = (t >= d) ? soff[t-d] : 0;
        __syncthreads();
        soff[t] += v;
        __syncthreads();
    }
    int excl = soff[t] - scnt[t];
    g_offs[t] = excl;
    g_cnt[t]  = scnt[t];
    scur[t] = excl;
    __syncthreads();
    #pragma unroll
    for (int r = 0; r < En/512; r++) {
        int e = r*512 + t;
        int pos = atomicAdd(&scur[eidx[e]], 1);
        g_elist[pos] = e;
    }
}

// ---------------- K3: edge projections GEMM + scatter-add ----------------
__global__ void k_scatter(const float* __restrict__ eattr, const int* __restrict__ eidx,
                          const float* __restrict__ Wme,
                          const float* __restrict__ Wte1, const float* __restrict__ Wte2,
                          const float* __restrict__ Wte3) {
    __shared__ __align__(16) float sA[EPB][128];
    int t = threadIdx.x, warp = t >> 5, lane = t & 31;
    int e0 = blockIdx.x * EPB + warp * EPW;
    int posMain[EPW], posT[EPW];
    #pragma unroll
    for (int i = 0; i < EPW; i++) {
        int e = e0 + i;
        *(float4*)&sA[warp*EPW + i][lane*4] = *(const float4*)&eattr[e*128 + lane*4];
        int sg = eidx[e], dg = eidx[En + e];
        int b = sg >> 7, s = sg & 127, d = dg & 127;
        posMain[i] = (b*Nn + s)*Nn + d;
        posT[i]    = (b*Nn + d)*Nn + s;
    }
    __syncwarp();
    const float (*sArows)[128] = (const float (*)[128])&sA[warp*EPW];
    unsigned long long acc[EPW][2] = {};
    GEMM44(Wme, sArows, acc)
    #pragma unroll
    for (int i = 0; i < EPW; i++) {
        float2 v01 = unpack2(acc[i][0]);
        float2 v23 = unpack2(acc[i][1]);
        float* dst = &g_msgE[posMain[i]*128 + lane*4];
        atomicAdd(dst + 0, v01.x);
        atomicAdd(dst + 1, v01.y);
        atomicAdd(dst + 2, v23.x);
        atomicAdd(dst + 3, v23.y);
    }
    if (lane < 24) {
        const float* W = (lane < 8) ? Wte1 : ((lane < 16) ? Wte2 : Wte3);
        int c = lane & 7;
        float acc2[EPW] = {};
        #pragma unroll 4
        for (int k = 0; k < 128; k += 4) {
            float w0 = W[(k+0)*8 + c], w1 = W[(k+1)*8 + c];
            float w2 = W[(k+2)*8 + c], w3 = W[(k+3)*8 + c];
            #pragma unroll
            for (int i = 0; i < EPW; i++) {
                float4 a = *(const float4*)&sA[warp*EPW + i][k];
                acc2[i] += a.x*w0 + a.y*w1 + a.z*w2 + a.w*w3;
            }
        }
        #pragma unroll
        for (int i = 0; i < EPW; i++) {
            if (lane < 8)       atomicAdd(&g_T1[posT[i]*8 + c], acc2[i]);
            else if (lane < 16) atomicAdd(&g_T2[posT[i]*8 + c], acc2[i]);
            else                atomicAdd(&g_te3[posMain[i]*8 + c], acc2[i]);
        }
    }
}

// ---------------- K4: fused gather+LN1+GEMM1+LN2+GEMM2+atomicMax ----------------
__global__ void k_mpnn(const int* __restrict__ eidx,
                       const float* __restrict__ ln1s, const float* __restrict__ ln1o,
                       const float* __restrict__ W1,
                       const float* __restrict__ ln2s, const float* __restrict__ ln2o,
                       const float* __restrict__ W2) {
    __shared__ __align__(16) float sY[EPB][128];
    int t = threadIdx.x, warp = t >> 5, lane = t & 31;
    int e0 = blockIdx.x * EPB + warp * EPW;
    int dglob[EPW];
    float4 s1 = *(const float4*)&ln1s[lane*4];
    float4 o1 = *(const float4*)&ln1o[lane*4];
    #pragma unroll
    for (int i = 0; i < EPW; i++) {
        int e = e0 + i;
        int sg = eidx[e], dg = eidx[En + e];
        int b = sg >> 7, s = sg & 127, d = dg & 127;
        dglob[i] = b*Nn + d;
        float4 x  = *(const float4*)&g_msgE[((b*Nn + s)*Nn + d)*128 + lane*4];
        float4 m1 = *(const float4*)&g_msg1[dglob[i]*128 + lane*4];
        float4 m2 = *(const float4*)&g_msg2[(b*Nn + s)*128 + lane*4];
        float4 mg = *(const float4*)&g_mgg[b*128 + lane*4];
        x.x += m1.x + m2.x + mg.x;
        x.y += m1.y + m2.y + mg.y;
        x.z += m1.z + m2.z + mg.z;
        x.w += m1.w + m2.w + mg.w;
        float mean = wredsum(x.x + x.y + x.z + x.w) * (1.f/128.f);
        float dx = x.x - mean, dy = x.y - mean, dz = x.z - mean, dw = x.w - mean;
        float var = wredsum(dx*dx + dy*dy + dz*dz + dw*dw) * (1.f/128.f);
        float rstd = rsqrtf(var + 1e-5f);
        float4 y;
        y.x = fmaxf(s1.x * dx * rstd + o1.x, 0.f);
        y.y = fmaxf(s1.y * dy * rstd + o1.y, 0.f);
        y.z = fmaxf(s1.z * dz * rstd + o1.z, 0.f);
        y.w = fmaxf(s1.w * dw * rstd + o1.w, 0.f);
        *(float4*)&sY[warp*EPW + i][lane*4] = y;
    }
    __syncwarp();
    const float (*sArows)[128] = (const float (*)[128])&sY[warp*EPW];
    float4 s2 = *(const float4*)&ln2s[lane*4];
    float4 o2 = *(const float4*)&ln2o[lane*4];
    {
        unsigned long long acc[EPW][2] = {};
        GEMM44(W1, sArows, acc)
        __syncwarp();
        #pragma unroll
        for (int i = 0; i < EPW; i++) {
            float2 v01 = unpack2(acc[i][0]);
            float2 v23 = unpack2(acc[i][1]);
            float mean = wredsum(v01.x + v01.y + v23.x + v23.y) * (1.f/128.f);
            float d0 = v01.x - mean, d1 = v01.y - mean;
            float d2 = v23.x - mean, d3 = v23.y - mean;
            float var = wredsum(d0*d0 + d1*d1 + d2*d2 + d3*d3) * (1.f/128.f);
            float rstd = rsqrtf(var + 1e-5f);
            float4 y;
            y.x = fmaxf(s2.x * d0 * rstd + o2.x, 0.f);
            y.y = fmaxf(s2.y * d1 * rstd + o2.y, 0.f);
            y.z = fmaxf(s2.z * d2 * rstd + o2.z, 0.f);
            y.w = fmaxf(s2.w * d3 * rstd + o2.w, 0.f);
            *(float4*)&sY[warp*EPW + i][lane*4] = y;
        }
    }
    __syncwarp();
    {
        unsigned long long acc[EPW][2] = {};
        GEMM44(W2, sArows, acc)
        #pragma unroll
        for (int i = 0; i < EPW; i++) {
            float2 v01 = unpack2(acc[i][0]);
            float2 v23 = unpack2(acc[i][1]);
            unsigned* dst = &g_maxacc[dglob[i]*128 + lane*4];
            atomicMax(dst + 0, fmap(v01.x));
            atomicMax(dst + 1, fmap(v01.y));
            atomicMax(dst + 2, fmap(v23.x));
            atomicMax(dst + 3, fmap(v23.y));
        }
    }
}

// ---------------- K5: grouped triplet kernel, warp-per-edge ----------------
// block = group g (512 blocks), 256 threads = 8 warps; X and Wu3 staged in smem.
__global__ void __launch_bounds__(256)
k_tri2(const int* __restrict__ eidx, const float* __restrict__ Wu3,
       float* __restrict__ out2) {
    __shared__ __align__(16) float sX[128][8];
    __shared__ __align__(16) float sW[8*128];
    __shared__ float sbase[8];
    int g = blockIdx.x;
    int cnt = g_cnt[g];
    if (cnt == 0) return;
    int off = g_offs[g];
    int t = threadIdx.x, warp = t >> 5, lane = t & 31;
    int b = g >> 7;
    if (t < 128) {
        float4 a0 = ((const float4*)g_t1)[(b*128 + t)*2];
        float4 a1 = ((const float4*)g_t1)[(b*128 + t)*2 + 1];
        float4 b0 = ((const float4*)g_T1)[(g*128 + t)*2];
        float4 b1 = ((const float4*)g_T1)[(g*128 + t)*2 + 1];
        float4 x0 = {a0.x+b0.x, a0.y+b0.y, a0.z+b0.z, a0.w+b0.w};
        float4 x1 = {a1.x+b1.x, a1.y+b1.y, a1.z+b1.z, a1.w+b1.w};
        *(float4*)&sX[t][0] = x0;
        *(float4*)&sX[t][4] = x1;
    }
    ((float4*)sW)[t] = ((const float4*)Wu3)[t];
    if (t < 8) sbase[t] = g_t2[g*8 + t] + g_tg[b*8 + t];
    __syncthreads();
    float4 base0 = *(float4*)&sbase[0];
    float4 base1 = *(float4*)&sbase[4];
    const float4* T2v  = (const float4*)g_T2;
    const float4* t3v  = (const float4*)g_t3;
    const float4* te3v = (const float4*)g_te3;
    for (int n = warp; n < cnt; n += 8) {
        int e = g_elist[off + n];
        int k = eidx[En + e] & 127;
        float v[8];
        #pragma unroll
        for (int q = 0; q < 8; q++) v[q] = -3.0e38f;
        #pragma unroll
        for (int ii = 0; ii < 4; ii++) {
            int i = ii*32 + lane;
            float4 c0 = T2v[((b*128 + k)*128 + i)*2];
            float4 c1 = T2v[((b*128 + k)*128 + i)*2 + 1];
            float4 x0 = *(const float4*)&sX[i][0];
            float4 x1 = *(const float4*)&sX[i][4];
            v[0] = fmaxf(v[0], x0.x + c0.x);
            v[1] = fmaxf(v[1], x0.y + c0.y);
            v[2] = fmaxf(v[2], x0.z + c0.z);
            v[3] = fmaxf(v[3], x0.w + c0.w);
            v[4] = fmaxf(v[4], x1.x + c1.x);
            v[5] = fmaxf(v[5], x1.y + c1.y);
            v[6] = fmaxf(v[6], x1.z + c1.z);
            v[7] = fmaxf(v[7], x1.w + c1.w);
        }
        #pragma unroll
        for (int o = 16; o; o >>= 1) {
            #pragma unroll
            for (int q = 0; q < 8; q++)
                v[q] = fmaxf(v[q], __shfl_xor_sync(0xffffffffu, v[q], o));
        }
        float4 t30 = t3v[(b*128 + k)*2],  t31 = t3v[(b*128 + k)*2 + 1];
        float4 e30 = te3v[(g*128 + k)*2], e31 = te3v[(g*128 + k)*2 + 1];
        float s[8];
        s[0] = v[0] + base0.x + t30.x + e30.x;
        s[1] = v[1] + base0.y + t30.y + e30.y;
        s[2] = v[2] + base0.z + t30.z + e30.z;
        s[3] = v[3] + base0.w + t30.w + e30.w;
        s[4] = v[4] + base1.x + t31.x + e31.x;
        s[5] = v[5] + base1.y + t31.y + e31.y;
        s[6] = v[6] + base1.z + t31.z + e31.z;
        s[7] = v[7] + base1.w + t31.w + e31.w;
        float4 acc = {0.f, 0.f, 0.f, 0.f};
        #pragma unroll
        for (int f = 0; f < 8; f++) {
            float4 w = *(const float4*)&sW[f*128 + lane*4];
            acc.x += s[f]*w.x;
            acc.y += s[f]*w.y;
            acc.z += s[f]*w.z;
            acc.w += s[f]*w.w;
        }
        acc.x = fmaxf(acc.x, 0.f);
        acc.y = fmaxf(acc.y, 0.f);
        acc.z = fmaxf(acc.z, 0.f);
        acc.w = fmaxf(acc.w, 0.f);
        *(float4*)&out2[e*128 + lane*4] = acc;
    }
}

// ---------------- K6: final ret = LN(u1 + max @ W_u2) ----------------
__global__ void k_final(const float* __restrict__ Wu2,
                        const float* __restrict__ lnfs, const float* __restrict__ lnfo,
                        float* __restrict__ out1) {
    __shared__ float sm[128];
    __shared__ float sred[4];
    int n = blockIdx.x, t = threadIdx.x;
    sm[t] = funmap(g_maxacc[n*128 + t]);
    __syncthreads();
    float acc = g_u1[n*128 + t];
    #pragma unroll 8
    for (int f = 0; f < 128; f++) acc += sm[f] * Wu2[f*128 + t];
    float mean = brsum(acc, sred, t) * (1.f/128.f);
    float dmu = acc - mean;
    float var = brsum(dmu*dmu, sred, t) * (1.f/128.f);
    out1[n*128 + t] = lnfs[t] * dmu * rsqrtf(var + 1e-5f) + lnfo[t];
}

// ---------------- launch (multi-stream fork/join inside capture) ----------------
extern "C" void kernel_launch(void* const* d_in, const int* in_sizes, int n_in,
                              void* d_out, int out_size) {
    const float* node_fts  = (const float*)d_in[0];
    const float* edge_attr = (const float*)d_in[1];
    const float* graph_fts = (const float*)d_in[2];
    const float* W_tri1 = (const float*)d_in[3];
    const float* W_tri2 = (const float*)d_in[4];
    const float* W_tri3 = (const float*)d_in[5];
    const float* W_te1  = (const float*)d_in[6];
    const float* W_te2  = (const float*)d_in[7];
    const float* W_te3  = (const float*)d_in[8];
    const float* W_tg   = (const float*)d_in[9];
    const float* W_m1   = (const float*)d_in[10];
    const float* W_m2   = (const float*)d_in[11];
    const float* W_me   = (const float*)d_in[12];
    const float* W_mg   = (const float*)d_in[13];
    const float* ln1_s  = (const float*)d_in[14];
    const float* ln1_o  = (const float*)d_in[15];
    const float* W_mlp1 = (const float*)d_in[16];
    const float* ln2_s  = (const float*)d_in[17];
    const float* ln2_o  = (const float*)d_in[18];
    const float* W_mlp2 = (const float*)d_in[19];
    const float* W_u1   = (const float*)d_in[20];
    const float* W_u2   = (const float*)d_in[21];
    const float* W_u3   = (const float*)d_in[22];
    const float* lnf_s  = (const float*)d_in[23];
    const float* lnf_o  = (const float*)d_in[24];
    const int*   eidx   = (const int*)d_in[25];

    float* out1 = (float*)d_out;                 // ret      [512,128]
    float* out2 = out1 + Bn*Nn*Cn;               // tri gath [8192,128]

    static cudaStream_t s2 = 0, s3 = 0;
    static cudaEvent_t eFork = 0, eProj = 0, eScat = 0, eTri = 0;
    if (!s2) {
        cudaStreamCreateWithFlags(&s2, cudaStreamNonBlocking);
        cudaStreamCreateWithFlags(&s3, cudaStreamNonBlocking);
        cudaEventCreateWithFlags(&eFork, cudaEventDisableTiming);
        cudaEventCreateWithFlags(&eProj, cudaEventDisableTiming);
        cudaEventCreateWithFlags(&eScat, cudaEventDisableTiming);
        cudaEventCreateWithFlags(&eTri,  cudaEventDisableTiming);
    }

    // fork
    cudaEventRecord(eFork, 0);
    cudaStreamWaitEvent(s2, eFork, 0);
    cudaStreamWaitEvent(s3, eFork, 0);

    // s2: projections (independent of init/scatter)
    k_proj<<<Bn*Nn + Bn, 128, 0, s2>>>(node_fts, graph_fts, W_m1, W_m2, W_u1,
                                       W_tri1, W_tri2, W_tri3, W_mg, W_tg);
    cudaEventRecord(eProj, s2);

    // s3: edge grouping (only needs eidx), runs concurrent with init/proj
    k_group<<<1, 512, 0, s3>>>(eidx);

    // main: init -> scatter
    int init_total = 3*A4 + B4 + C4;
    k_init<<<(init_total + 255)/256, 256>>>(eidx);
    k_scatter<<<En/EPB, 256>>>(edge_attr, eidx, W_me, W_te1, W_te2, W_te3);
    cudaEventRecord(eScat, 0);

    // s3: triplet path (needs scatter + proj + groups), concurrent with k_mpnn
    cudaStreamWaitEvent(s3, eScat, 0);
    cudaStreamWaitEvent(s3, eProj, 0);
    k_tri2<<<Bn*Nn, 256, 0, s3>>>(eidx, W_u3, out2);
    cudaEventRecord(eTri, s3);

    // main: mpnn (needs scatter + proj) -> final
    cudaStreamWaitEvent(0, eProj, 0);
    k_mpnn<<<En/EPB, 256>>>(eidx, ln1_s, ln1_o, W_mlp1, ln2_s, ln2_o, W_mlp2);
    k_final<<<Bn*Nn, 128>>>(W_u2, lnf_s, lnf_o, out1);

    // join
    cudaStreamWaitEvent(0, eTri, 0);
}